// round 1
// baseline (speedup 1.0000x reference)
#include <cuda_runtime.h>
#include <math.h>

#define NN 1024
#define DIM 512
#define QKVD 1536
#define HEADS 8
#define HD 64

// Scratch (static device allocation is allowed; runtime alloc is not).
__device__ float g_qkv[NN * QKVD];          // [n, 3*512]  (q|k|v per row)
__device__ float g_S[(size_t)HEADS * NN * NN]; // [h, n, m]  bias -> scores -> probs

// ---------------------------------------------------------------------------
// K1: g_qkv[n, j] = sum_k x[n,k] * Wqkv[j,k]    (M=1024, N=1536, K=512)
// 64x64 block tile, BK=16, 256 threads, 4x4 per-thread microtile.
// ---------------------------------------------------------------------------
__global__ void __launch_bounds__(256) qkv_gemm(const float* __restrict__ x,
                                                const float* __restrict__ W) {
    __shared__ float As[16][65];
    __shared__ float Bs[16][65];
    const int t  = threadIdx.x;
    const int tx = t & 15, ty = t >> 4;
    const int bm = blockIdx.y * 64, bn = blockIdx.x * 64;
    const int lr = t >> 2;          // row within tile 0..63
    const int lk = (t & 3) * 4;     // k offset 0,4,8,12

    float acc[4][4] = {};
    for (int k0 = 0; k0 < DIM; k0 += 16) {
        float4 a = *(const float4*)(x + (size_t)(bm + lr) * DIM + k0 + lk);
        float4 b = *(const float4*)(W + (size_t)(bn + lr) * DIM + k0 + lk);
        __syncthreads();
        As[lk + 0][lr] = a.x; As[lk + 1][lr] = a.y; As[lk + 2][lr] = a.z; As[lk + 3][lr] = a.w;
        Bs[lk + 0][lr] = b.x; Bs[lk + 1][lr] = b.y; Bs[lk + 2][lr] = b.z; Bs[lk + 3][lr] = b.w;
        __syncthreads();
#pragma unroll
        for (int k = 0; k < 16; k++) {
            float ar[4], br[4];
#pragma unroll
            for (int i = 0; i < 4; i++) ar[i] = As[k][ty * 4 + i];
#pragma unroll
            for (int j = 0; j < 4; j++) br[j] = Bs[k][tx * 4 + j];
#pragma unroll
            for (int i = 0; i < 4; i++)
#pragma unroll
                for (int j = 0; j < 4; j++)
                    acc[i][j] = fmaf(ar[i], br[j], acc[i][j]);
        }
    }
#pragma unroll
    for (int i = 0; i < 4; i++)
#pragma unroll
        for (int j = 0; j < 4; j++)
            g_qkv[(size_t)(bm + ty * 4 + i) * QKVD + bn + tx * 4 + j] = acc[i][j];
}

// ---------------------------------------------------------------------------
// K2: location bias. One thread per (n, m) pair. Writes
//   g_S[h, n, m] = log(relu(emb(n,m) . W_loc[h] + b_loc[h]) + 1e-6)
// emb computed once per pair, reused across all 8 heads.
// ---------------------------------------------------------------------------
__global__ void __launch_bounds__(256) loc_bias(const float* __restrict__ locs,
                                                const float* __restrict__ Wl,
                                                const float* __restrict__ bl) {
    __shared__ float sW[8][64];
    __shared__ float sb[8];
    const int t = threadIdx.x;
    for (int i = t; i < 512; i += 256) sW[i >> 6][i & 63] = Wl[i];
    if (t < 8) sb[t] = bl[t];
    __syncthreads();

    const int n = blockIdx.y;
    const int m = blockIdx.x * 256 + t;

    const float4 bn = ((const float4*)locs)[n];
    const float4 bm = ((const float4*)locs)[m];
    const float wn = bn.z - bn.x + 1.0f, hn = bn.w - bn.y + 1.0f;
    const float wm = bm.z - bm.x + 1.0f, hm = bm.w - bm.y + 1.0f;
    const float cxn = 0.5f * (bn.x + bn.z), cyn = 0.5f * (bn.y + bn.w);
    const float cxm = 0.5f * (bm.x + bm.z), cym = 0.5f * (bm.y + bm.w);

    float pos[4];
    pos[0] = logf(fmaxf(fabsf((cxn - cxm) / wn), 1e-3f));
    pos[1] = logf(fmaxf(fabsf((cyn - cym) / hn), 1e-3f));
    pos[2] = logf(wm / wn);
    pos[3] = logf(hm / hn);

    // 100 / 1000^(j/8)
    const float invd[8] = {100.0f, 42.1696503f, 17.7827941f, 7.49894209f,
                           3.16227766f, 1.33352143f, 0.562341325f, 0.237137371f};

    float acc[8];
#pragma unroll
    for (int h = 0; h < 8; h++) acc[h] = sb[h];

#pragma unroll
    for (int g = 0; g < 4; g++) {
#pragma unroll
        for (int j = 0; j < 8; j++) {
            float s, c;
            __sincosf(pos[g] * invd[j], &s, &c);
#pragma unroll
            for (int h = 0; h < 8; h++)
                acc[h] = fmaf(s, sW[h][g * 16 + j],
                              fmaf(c, sW[h][g * 16 + 8 + j], acc[h]));
        }
    }

    const size_t base = (size_t)n * NN + m;
#pragma unroll
    for (int h = 0; h < 8; h++) {
        float v = fmaxf(acc[h], 0.0f);
        g_S[(size_t)h * NN * NN + base] = logf(v + 1e-6f);
    }
}

// ---------------------------------------------------------------------------
// K3: per-head scores  S[h,n,m] = bias + 0.125 * sum_d Q[n,d] K[m,d]
// ---------------------------------------------------------------------------
__global__ void __launch_bounds__(256) score_gemm() {
    __shared__ float As[16][65];
    __shared__ float Bs[16][65];
    const int t  = threadIdx.x;
    const int tx = t & 15, ty = t >> 4;
    const int h  = blockIdx.z;
    const int bm = blockIdx.y * 64;  // query rows
    const int bn = blockIdx.x * 64;  // key cols
    const int lr = t >> 2;
    const int lk = (t & 3) * 4;

    const float* Q = g_qkv + h * HD;
    const float* K = g_qkv + DIM + h * HD;

    float acc[4][4] = {};
    for (int k0 = 0; k0 < HD; k0 += 16) {
        float4 a = *(const float4*)(Q + (size_t)(bm + lr) * QKVD + k0 + lk);
        float4 b = *(const float4*)(K + (size_t)(bn + lr) * QKVD + k0 + lk);
        __syncthreads();
        As[lk + 0][lr] = a.x; As[lk + 1][lr] = a.y; As[lk + 2][lr] = a.z; As[lk + 3][lr] = a.w;
        Bs[lk + 0][lr] = b.x; Bs[lk + 1][lr] = b.y; Bs[lk + 2][lr] = b.z; Bs[lk + 3][lr] = b.w;
        __syncthreads();
#pragma unroll
        for (int k = 0; k < 16; k++) {
            float ar[4], br[4];
#pragma unroll
            for (int i = 0; i < 4; i++) ar[i] = As[k][ty * 4 + i];
#pragma unroll
            for (int j = 0; j < 4; j++) br[j] = Bs[k][tx * 4 + j];
#pragma unroll
            for (int i = 0; i < 4; i++)
#pragma unroll
                for (int j = 0; j < 4; j++)
                    acc[i][j] = fmaf(ar[i], br[j], acc[i][j]);
        }
    }
    float* S = g_S + (size_t)h * NN * NN;
#pragma unroll
    for (int i = 0; i < 4; i++)
#pragma unroll
        for (int j = 0; j < 4; j++) {
            size_t idx = (size_t)(bm + ty * 4 + i) * NN + bn + tx * 4 + j;
            S[idx] = fmaf(0.125f, acc[i][j], S[idx]);
        }
}

// ---------------------------------------------------------------------------
// K4: row softmax over m. One block per (h,n) row; 256 threads x float4.
// ---------------------------------------------------------------------------
__global__ void __launch_bounds__(256) softmax_k() {
    __shared__ float redmax[8];
    __shared__ float redsum[8];
    const size_t row = blockIdx.x;  // 0 .. 8191
    float4* p = (float4*)(g_S + row * NN);
    const int t = threadIdx.x;

    float4 v = p[t];
    float mx = fmaxf(fmaxf(v.x, v.y), fmaxf(v.z, v.w));
#pragma unroll
    for (int o = 16; o; o >>= 1) mx = fmaxf(mx, __shfl_xor_sync(0xffffffffu, mx, o));
    if ((t & 31) == 0) redmax[t >> 5] = mx;
    __syncthreads();
    float rowmax = redmax[0];
#pragma unroll
    for (int i = 1; i < 8; i++) rowmax = fmaxf(rowmax, redmax[i]);

    v.x = __expf(v.x - rowmax);
    v.y = __expf(v.y - rowmax);
    v.z = __expf(v.z - rowmax);
    v.w = __expf(v.w - rowmax);
    float s = v.x + v.y + v.z + v.w;
#pragma unroll
    for (int o = 16; o; o >>= 1) s += __shfl_xor_sync(0xffffffffu, s, o);
    if ((t & 31) == 0) redsum[t >> 5] = s;
    __syncthreads();
    float total = 0.0f;
#pragma unroll
    for (int i = 0; i < 8; i++) total += redsum[i];

    const float inv = 1.0f / total;
    v.x *= inv; v.y *= inv; v.z *= inv; v.w *= inv;
    p[t] = v;
}

// ---------------------------------------------------------------------------
// K5: out[n, h*64+d] = sum_m P[h,n,m] * V[m, h*64+d]
// ---------------------------------------------------------------------------
__global__ void __launch_bounds__(256) pv_gemm(float* __restrict__ out) {
    __shared__ float As[16][65];
    __shared__ float Bs[16][64];
    const int t  = threadIdx.x;
    const int tx = t & 15, ty = t >> 4;
    const int h  = blockIdx.y;
    const int bm = blockIdx.x * 64;   // query rows
    const int lr = t >> 2;            // A tile row 0..63
    const int lk = (t & 3) * 4;       // A tile k 0,4,8,12
    const int br = t >> 4;            // B tile row (k) 0..15
    const int bd = (t & 15) * 4;      // B tile col (d) 0..60

    const float* P = g_S + (size_t)h * NN * NN;
    const float* V = g_qkv + 2 * DIM + h * HD;

    float acc[4][4] = {};
    for (int k0 = 0; k0 < NN; k0 += 16) {
        float4 a = *(const float4*)(P + (size_t)(bm + lr) * NN + k0 + lk);
        float4 b = *(const float4*)(V + (size_t)(k0 + br) * QKVD + bd);
        __syncthreads();
        As[lk + 0][lr] = a.x; As[lk + 1][lr] = a.y; As[lk + 2][lr] = a.z; As[lk + 3][lr] = a.w;
        *(float4*)&Bs[br][bd] = b;
        __syncthreads();
#pragma unroll
        for (int k = 0; k < 16; k++) {
            float ar[4], brg[4];
#pragma unroll
            for (int i = 0; i < 4; i++) ar[i] = As[k][ty * 4 + i];
#pragma unroll
            for (int j = 0; j < 4; j++) brg[j] = Bs[k][tx * 4 + j];
#pragma unroll
            for (int i = 0; i < 4; i++)
#pragma unroll
                for (int j = 0; j < 4; j++)
                    acc[i][j] = fmaf(ar[i], brg[j], acc[i][j]);
        }
    }
#pragma unroll
    for (int i = 0; i < 4; i++)
#pragma unroll
        for (int j = 0; j < 4; j++)
            out[(size_t)(bm + ty * 4 + i) * DIM + h * HD + tx * 4 + j] = acc[i][j];
}

// ---------------------------------------------------------------------------
extern "C" void kernel_launch(void* const* d_in, const int* in_sizes, int n_in,
                              void* d_out, int out_size) {
    const float* x    = (const float*)d_in[0];
    // d_in[1] = x_reg : unused by the reference
    const float* locs = (const float*)d_in[2];
    const float* Wqkv = (const float*)d_in[3];
    const float* Wloc = (const float*)d_in[4];
    const float* bloc = (const float*)d_in[5];
    float* out = (float*)d_out;

    qkv_gemm<<<dim3(QKVD / 64, NN / 64), 256>>>(x, Wqkv);
    loc_bias<<<dim3(NN / 256, NN), 256>>>(locs, Wloc, bloc);
    score_gemm<<<dim3(NN / 64, NN / 64, HEADS), 256>>>();
    softmax_k<<<HEADS * NN, 256>>>();
    pv_gemm<<<dim3(NN / 64, HEADS), 256>>>(out);
}

// round 2
// speedup vs baseline: 1.1022x; 1.1022x over previous
#include <cuda_runtime.h>
#include <math.h>

#define NN 1024
#define DIM 512
#define QKVD 1536
#define HEADS 8
#define HD 64
#define BM 32
#define BN 64

// Scratch (static device allocation is allowed; runtime alloc is not).
__device__ float g_qkv[NN * QKVD];             // [n, 3*512]  (q|k|v per row)
__device__ float g_S[(size_t)HEADS * NN * NN]; // [h, n, m]   location bias (log term)

// ---------------------------------------------------------------------------
// K1: g_qkv[n, j] = sum_k x[n,k] * Wqkv[j,k]    (M=1024, N=1536, K=512)
// ---------------------------------------------------------------------------
__global__ void __launch_bounds__(256) qkv_gemm(const float* __restrict__ x,
                                                const float* __restrict__ W) {
    __shared__ float As[16][65];
    __shared__ float Bs[16][65];
    const int t  = threadIdx.x;
    const int tx = t & 15, ty = t >> 4;
    const int bm = blockIdx.y * 64, bn = blockIdx.x * 64;
    const int lr = t >> 2;
    const int lk = (t & 3) * 4;

    float acc[4][4] = {};
    for (int k0 = 0; k0 < DIM; k0 += 16) {
        float4 a = *(const float4*)(x + (size_t)(bm + lr) * DIM + k0 + lk);
        float4 b = *(const float4*)(W + (size_t)(bn + lr) * DIM + k0 + lk);
        __syncthreads();
        As[lk + 0][lr] = a.x; As[lk + 1][lr] = a.y; As[lk + 2][lr] = a.z; As[lk + 3][lr] = a.w;
        Bs[lk + 0][lr] = b.x; Bs[lk + 1][lr] = b.y; Bs[lk + 2][lr] = b.z; Bs[lk + 3][lr] = b.w;
        __syncthreads();
#pragma unroll
        for (int k = 0; k < 16; k++) {
            float ar[4], br[4];
#pragma unroll
            for (int i = 0; i < 4; i++) ar[i] = As[k][ty * 4 + i];
#pragma unroll
            for (int j = 0; j < 4; j++) br[j] = Bs[k][tx * 4 + j];
#pragma unroll
            for (int i = 0; i < 4; i++)
#pragma unroll
                for (int j = 0; j < 4; j++)
                    acc[i][j] = fmaf(ar[i], br[j], acc[i][j]);
        }
    }
#pragma unroll
    for (int i = 0; i < 4; i++)
#pragma unroll
        for (int j = 0; j < 4; j++)
            g_qkv[(size_t)(bm + ty * 4 + i) * QKVD + bn + tx * 4 + j] = acc[i][j];
}

// ---------------------------------------------------------------------------
// K2: location bias (fast-math logs). g_S[h,n,m] = log(relu(emb.Wl+b)+1e-6)
// ---------------------------------------------------------------------------
__global__ void __launch_bounds__(256) loc_bias(const float* __restrict__ locs,
                                                const float* __restrict__ Wl,
                                                const float* __restrict__ bl) {
    __shared__ float sW[8][64];
    __shared__ float sb[8];
    const int t = threadIdx.x;
    for (int i = t; i < 512; i += 256) sW[i >> 6][i & 63] = Wl[i];
    if (t < 8) sb[t] = bl[t];
    __syncthreads();

    const int n = blockIdx.y;
    const int m = blockIdx.x * 256 + t;

    const float4 bn = ((const float4*)locs)[n];
    const float4 bm = ((const float4*)locs)[m];
    const float wn = bn.z - bn.x + 1.0f, hn = bn.w - bn.y + 1.0f;
    const float wm = bm.z - bm.x + 1.0f, hm = bm.w - bm.y + 1.0f;
    const float cxn = 0.5f * (bn.x + bn.z), cyn = 0.5f * (bn.y + bn.w);
    const float cxm = 0.5f * (bm.x + bm.z), cym = 0.5f * (bm.y + bm.w);

    float pos[4];
    pos[0] = __logf(fmaxf(fabsf((cxn - cxm) / wn), 1e-3f));
    pos[1] = __logf(fmaxf(fabsf((cyn - cym) / hn), 1e-3f));
    pos[2] = __logf(wm / wn);
    pos[3] = __logf(hm / hn);

    const float invd[8] = {100.0f, 42.1696503f, 17.7827941f, 7.49894209f,
                           3.16227766f, 1.33352143f, 0.562341325f, 0.237137371f};

    float acc[8];
#pragma unroll
    for (int h = 0; h < 8; h++) acc[h] = sb[h];

#pragma unroll
    for (int g = 0; g < 4; g++) {
#pragma unroll
        for (int j = 0; j < 8; j++) {
            float s, c;
            __sincosf(pos[g] * invd[j], &s, &c);
#pragma unroll
            for (int h = 0; h < 8; h++)
                acc[h] = fmaf(s, sW[h][g * 16 + j],
                              fmaf(c, sW[h][g * 16 + 8 + j], acc[h]));
        }
    }

    const size_t base = (size_t)n * NN + m;
#pragma unroll
    for (int h = 0; h < 8; h++) {
        float v = fmaxf(acc[h], 0.0f);
        g_S[(size_t)h * NN * NN + base] = __logf(v + 1e-6f);
    }
}

// ---------------------------------------------------------------------------
// K3 (fused): per (head, 32-row q-tile) flash attention.
//   S = bias + 0.125*Q K^T ; online softmax ; O = P V ; write output.
// 256 threads: 16x16; thread owns 2 rows x 4 cols of each 32x64 tile.
// ---------------------------------------------------------------------------
__global__ void __launch_bounds__(256) fused_attn(float* __restrict__ out) {
    __shared__ float Qs[BM][68];
    __shared__ float KP[BN][68];   // K^T (d-major) during S phase; P (rows 0..31) after
    __shared__ float Vs[BN][68];

    const int t  = threadIdx.x;
    const int tx = t & 15, ty = t >> 4;
    const int h  = blockIdx.y;
    const int bm = blockIdx.x * BM;
    const int r0 = ty * 2, r1 = r0 + 1;

    // Load Q tile [32][64]
    {
        const int qr = t >> 3;
        const int qc = (t & 7) * 8;
        const float* Q = g_qkv + (size_t)(bm + qr) * QKVD + h * HD + qc;
        float4 a = *(const float4*)Q;
        float4 b = *(const float4*)(Q + 4);
        *(float4*)&Qs[qr][qc] = a;
        *(float4*)&Qs[qr][qc + 4] = b;
    }

    float O[2][4] = {};
    float rmax0 = -INFINITY, rmax1 = -INFINITY;
    float rsum0 = 0.0f, rsum1 = 0.0f;

    const float* Kg = g_qkv + DIM + h * HD;
    const float* Vg = g_qkv + 2 * DIM + h * HD;
    const float* Bg = g_S + (size_t)h * NN * NN;

    const int lr  = t >> 2;        // 0..63 tile row for loads
    const int lc0 = (t & 3) * 4;   // 0,4,8,12

    for (int mt = 0; mt < NN / BN; mt++) {
        const int mbase = mt * BN;
        __syncthreads();  // previous iter's KP/Vs fully consumed

        // Load K (transposed into KP[d][m]) and V (Vs[m][d])
#pragma unroll
        for (int p = 0; p < 4; p++) {
            const int d = p * 16 + lc0;
            float4 k4 = *(const float4*)(Kg + (size_t)(mbase + lr) * QKVD + d);
            float4 v4 = *(const float4*)(Vg + (size_t)(mbase + lr) * QKVD + d);
            KP[d + 0][lr] = k4.x; KP[d + 1][lr] = k4.y;
            KP[d + 2][lr] = k4.z; KP[d + 3][lr] = k4.w;
            *(float4*)&Vs[lr][d] = v4;
        }
        // Bias for this thread's 2x4 fragment (global; overlaps with smem fill)
        float4 b0 = *(const float4*)(Bg + (size_t)(bm + r0) * NN + mbase + tx * 4);
        float4 b1 = *(const float4*)(Bg + (size_t)(bm + r1) * NN + mbase + tx * 4);
        __syncthreads();

        // S = 0.125 * Q K^T + bias
        float a0[4] = {}, a1[4] = {};
#pragma unroll
        for (int d = 0; d < 64; d++) {
            const float q0 = Qs[r0][d];
            const float q1 = Qs[r1][d];
            const float4 k = *(const float4*)&KP[d][tx * 4];
            a0[0] = fmaf(q0, k.x, a0[0]); a0[1] = fmaf(q0, k.y, a0[1]);
            a0[2] = fmaf(q0, k.z, a0[2]); a0[3] = fmaf(q0, k.w, a0[3]);
            a1[0] = fmaf(q1, k.x, a1[0]); a1[1] = fmaf(q1, k.y, a1[1]);
            a1[2] = fmaf(q1, k.z, a1[2]); a1[3] = fmaf(q1, k.w, a1[3]);
        }
        float s0[4], s1[4];
        s0[0] = fmaf(0.125f, a0[0], b0.x); s0[1] = fmaf(0.125f, a0[1], b0.y);
        s0[2] = fmaf(0.125f, a0[2], b0.z); s0[3] = fmaf(0.125f, a0[3], b0.w);
        s1[0] = fmaf(0.125f, a1[0], b1.x); s1[1] = fmaf(0.125f, a1[1], b1.y);
        s1[2] = fmaf(0.125f, a1[2], b1.z); s1[3] = fmaf(0.125f, a1[3], b1.w);

        // Row max across the 16 tx lanes (within a 16-lane half warp)
        float m0 = fmaxf(fmaxf(s0[0], s0[1]), fmaxf(s0[2], s0[3]));
        float m1 = fmaxf(fmaxf(s1[0], s1[1]), fmaxf(s1[2], s1[3]));
#pragma unroll
        for (int o = 8; o; o >>= 1) {
            m0 = fmaxf(m0, __shfl_xor_sync(0xffffffffu, m0, o));
            m1 = fmaxf(m1, __shfl_xor_sync(0xffffffffu, m1, o));
        }
        const float nm0 = fmaxf(rmax0, m0);
        const float nm1 = fmaxf(rmax1, m1);
        const float al0 = __expf(rmax0 - nm0);
        const float al1 = __expf(rmax1 - nm1);
        rmax0 = nm0; rmax1 = nm1;

        float p0[4], p1[4];
#pragma unroll
        for (int j = 0; j < 4; j++) {
            p0[j] = __expf(s0[j] - nm0);
            p1[j] = __expf(s1[j] - nm1);
        }
        float ls0 = p0[0] + p0[1] + p0[2] + p0[3];
        float ls1 = p1[0] + p1[1] + p1[2] + p1[3];
#pragma unroll
        for (int o = 8; o; o >>= 1) {
            ls0 += __shfl_xor_sync(0xffffffffu, ls0, o);
            ls1 += __shfl_xor_sync(0xffffffffu, ls1, o);
        }
        rsum0 = rsum0 * al0 + ls0;
        rsum1 = rsum1 * al1 + ls1;
#pragma unroll
        for (int j = 0; j < 4; j++) { O[0][j] *= al0; O[1][j] *= al1; }

        __syncthreads();  // all threads done reading KP (K^T)
        *(float4*)&KP[r0][tx * 4] = make_float4(p0[0], p0[1], p0[2], p0[3]);
        *(float4*)&KP[r1][tx * 4] = make_float4(p1[0], p1[1], p1[2], p1[3]);
        __syncthreads();  // P visible

        // O += P V
#pragma unroll
        for (int m = 0; m < 64; m++) {
            const float pa0 = KP[r0][m];
            const float pa1 = KP[r1][m];
            const float4 v = *(const float4*)&Vs[m][tx * 4];
            O[0][0] = fmaf(pa0, v.x, O[0][0]); O[0][1] = fmaf(pa0, v.y, O[0][1]);
            O[0][2] = fmaf(pa0, v.z, O[0][2]); O[0][3] = fmaf(pa0, v.w, O[0][3]);
            O[1][0] = fmaf(pa1, v.x, O[1][0]); O[1][1] = fmaf(pa1, v.y, O[1][1]);
            O[1][2] = fmaf(pa1, v.z, O[1][2]); O[1][3] = fmaf(pa1, v.w, O[1][3]);
        }
    }

    const float inv0 = 1.0f / rsum0;
    const float inv1 = 1.0f / rsum1;
    float* o0 = out + (size_t)(bm + r0) * DIM + h * HD + tx * 4;
    float* o1 = out + (size_t)(bm + r1) * DIM + h * HD + tx * 4;
    *(float4*)o0 = make_float4(O[0][0] * inv0, O[0][1] * inv0, O[0][2] * inv0, O[0][3] * inv0);
    *(float4*)o1 = make_float4(O[1][0] * inv1, O[1][1] * inv1, O[1][2] * inv1, O[1][3] * inv1);
}

// ---------------------------------------------------------------------------
extern "C" void kernel_launch(void* const* d_in, const int* in_sizes, int n_in,
                              void* d_out, int out_size) {
    const float* x    = (const float*)d_in[0];
    // d_in[1] = x_reg : unused by the reference
    const float* locs = (const float*)d_in[2];
    const float* Wqkv = (const float*)d_in[3];
    const float* Wloc = (const float*)d_in[4];
    const float* bloc = (const float*)d_in[5];
    float* out = (float*)d_out;

    qkv_gemm<<<dim3(QKVD / 64, NN / 64), 256>>>(x, Wqkv);
    loc_bias<<<dim3(NN / 256, NN), 256>>>(locs, Wloc, bloc);
    fused_attn<<<dim3(NN / BM, HEADS), 256>>>(out);
}

// round 3
// speedup vs baseline: 1.4638x; 1.3281x over previous
#include <cuda_runtime.h>
#include <math.h>

#define NN 1024
#define DIM 512
#define QKVD 1536
#define HEADS 8
#define HD 64
#define BM 64

#define QKV_MT 128     // qkv tile M
#define QKV_NT 64      // qkv tile N
#define QKV_BLOCKS ((NN / QKV_MT) * (QKVD / QKV_NT))   // 8*24 = 192
#define LOC_BLOCKS (NN * NN / 256)                      // 4096

// Scratch (static device allocation is allowed; runtime alloc is not).
__device__ float g_qkv[NN * QKVD];             // [n, 3*512]  (q|k|v per row)
__device__ float g_S[(size_t)HEADS * NN * NN]; // [h, n, m]   location bias (log term)

// ---------------------------------------------------------------------------
// K1 (combined): blocks [0,192) do the QKV GEMM tile; blocks [192, 4288) do
// the location-bias pairs. One launch -> loc blocks hide gemm latency.
// ---------------------------------------------------------------------------
struct SmemQkv {
    float As[8][132];   // [k][m] transposed, stride 132 (528B, 16B-aligned)
    float Bs[8][68];    // [k][n] transposed, stride 68  (272B, 16B-aligned)
};
struct SmemLoc {
    float sW[8][64];
    float sb[8];
};

__global__ void __launch_bounds__(256) fused_pre(const float* __restrict__ x,
                                                 const float* __restrict__ W,
                                                 const float* __restrict__ locs,
                                                 const float* __restrict__ Wl,
                                                 const float* __restrict__ bl) {
    __shared__ char smem_raw[sizeof(SmemQkv)];
    const int t = threadIdx.x;

    if (blockIdx.x < QKV_BLOCKS) {
        // ---------------- QKV GEMM: 128x64 tile, BK=8, 8x4 microtile --------
        SmemQkv* s = (SmemQkv*)smem_raw;
        const int qb = blockIdx.x;
        const int bm = (qb % (NN / QKV_MT)) * QKV_MT;
        const int bn = (qb / (NN / QKV_MT)) * QKV_NT;
        const int tx = t & 15, ty = t >> 4;

        const int ar = t >> 1;            // A row 0..127
        const int akc = (t & 1) * 4;      // A k-chunk 0|4
        const int br = t >> 1;            // B row 0..63 (t<128)
        const int bkc = (t & 1) * 4;

        const float* Ap = x + (size_t)(bm + ar) * DIM + akc;
        const float* Bp = W + (size_t)(bn + (br & 63)) * DIM + bkc;

        float4 ra = *(const float4*)Ap;
        float4 rb = (t < 128) ? *(const float4*)Bp : make_float4(0, 0, 0, 0);

        float acc[8][4] = {};
        for (int k0 = 0; k0 < DIM; k0 += 8) {
            __syncthreads();
            s->As[akc + 0][ar] = ra.x; s->As[akc + 1][ar] = ra.y;
            s->As[akc + 2][ar] = ra.z; s->As[akc + 3][ar] = ra.w;
            if (t < 128) {
                s->Bs[bkc + 0][br] = rb.x; s->Bs[bkc + 1][br] = rb.y;
                s->Bs[bkc + 2][br] = rb.z; s->Bs[bkc + 3][br] = rb.w;
            }
            __syncthreads();
            if (k0 + 8 < DIM) {
                ra = *(const float4*)(Ap + k0 + 8);
                if (t < 128) rb = *(const float4*)(Bp + k0 + 8);
            }
#pragma unroll
            for (int k = 0; k < 8; k++) {
                float4 a0 = *(const float4*)&s->As[k][ty * 8];
                float4 a1 = *(const float4*)&s->As[k][ty * 8 + 4];
                float4 b  = *(const float4*)&s->Bs[k][tx * 4];
                const float av[8] = {a0.x, a0.y, a0.z, a0.w, a1.x, a1.y, a1.z, a1.w};
#pragma unroll
                for (int i = 0; i < 8; i++) {
                    acc[i][0] = fmaf(av[i], b.x, acc[i][0]);
                    acc[i][1] = fmaf(av[i], b.y, acc[i][1]);
                    acc[i][2] = fmaf(av[i], b.z, acc[i][2]);
                    acc[i][3] = fmaf(av[i], b.w, acc[i][3]);
                }
            }
        }
#pragma unroll
        for (int i = 0; i < 8; i++)
            *(float4*)&g_qkv[(size_t)(bm + ty * 8 + i) * QKVD + bn + tx * 4] =
                make_float4(acc[i][0], acc[i][1], acc[i][2], acc[i][3]);
    } else {
        // ---------------- Location bias ------------------------------------
        SmemLoc* s = (SmemLoc*)smem_raw;
        for (int i = t; i < 512; i += 256) s->sW[i >> 6][i & 63] = Wl[i];
        if (t < 8) s->sb[t] = bl[t];
        __syncthreads();

        const int lid = blockIdx.x - QKV_BLOCKS;
        const int n = lid >> 2;
        const int m = (lid & 3) * 256 + t;

        const float4 bn = ((const float4*)locs)[n];
        const float4 bm = ((const float4*)locs)[m];
        const float wn = bn.z - bn.x + 1.0f, hn = bn.w - bn.y + 1.0f;
        const float wm = bm.z - bm.x + 1.0f, hm = bm.w - bm.y + 1.0f;
        const float cxn = 0.5f * (bn.x + bn.z), cyn = 0.5f * (bn.y + bn.w);
        const float cxm = 0.5f * (bm.x + bm.z), cym = 0.5f * (bm.y + bm.w);

        float pos[4];
        pos[0] = __logf(fmaxf(fabsf((cxn - cxm) / wn), 1e-3f));
        pos[1] = __logf(fmaxf(fabsf((cyn - cym) / hn), 1e-3f));
        pos[2] = __logf(wm / wn);
        pos[3] = __logf(hm / hn);

        const float invd[8] = {100.0f, 42.1696503f, 17.7827941f, 7.49894209f,
                               3.16227766f, 1.33352143f, 0.562341325f, 0.237137371f};

        float acc[8];
#pragma unroll
        for (int h = 0; h < 8; h++) acc[h] = s->sb[h];

#pragma unroll
        for (int g = 0; g < 4; g++) {
#pragma unroll
            for (int j = 0; j < 8; j++) {
                float sn, cs;
                __sincosf(pos[g] * invd[j], &sn, &cs);
#pragma unroll
                for (int h = 0; h < 8; h++)
                    acc[h] = fmaf(sn, s->sW[h][g * 16 + j],
                                  fmaf(cs, s->sW[h][g * 16 + 8 + j], acc[h]));
            }
        }
        const size_t base = (size_t)n * NN + m;
#pragma unroll
        for (int h = 0; h < 8; h++)
            g_S[(size_t)h * NN * NN + base] = __logf(fmaxf(acc[h], 0.0f) + 1e-6f);
    }
}

// ---------------------------------------------------------------------------
// K2 (fused flash attention): per (head, 64-row q-tile).
// 256 threads as 16x16; thread owns 4 rows x 4 cols of each 64x64 tile.
// smem: exactly 48 KB (3 x 64x64 fp32, stride 64).
// ---------------------------------------------------------------------------
__global__ void __launch_bounds__(256) fused_attn(float* __restrict__ out) {
    __shared__ float Qs[64][64];   // [r][d] row-major
    __shared__ float KP[64][64];   // K^T [d][m] during S; P [r][m] during PV
    __shared__ float Vs[64][64];   // [m][d]

    const int t  = threadIdx.x;
    const int tx = t & 15, ty = t >> 4;
    const int h  = blockIdx.x & 7;
    const int bm = (blockIdx.x >> 3) * BM;
    const int r0 = ty * 4;

    // Load Q tile [64][64]
    {
        const int qr = t >> 2;
        const int lc = (t & 3) * 4;
        const float* Q = g_qkv + (size_t)(bm + qr) * QKVD + h * HD;
#pragma unroll
        for (int p = 0; p < 4; p++)
            *(float4*)&Qs[qr][p * 16 + lc] = *(const float4*)(Q + p * 16 + lc);
    }

    float O[4][4] = {};
    float rmax[4] = {-INFINITY, -INFINITY, -INFINITY, -INFINITY};
    float rsum[4] = {};

    const float* Kg = g_qkv + DIM + h * HD;
    const float* Vg = g_qkv + 2 * DIM + h * HD;
    const float* Bg = g_S + (size_t)h * NN * NN;

    const int lr  = t >> 2;
    const int lc0 = (t & 3) * 4;

    for (int mt = 0; mt < NN / 64; mt++) {
        const int mbase = mt * 64;
        __syncthreads();  // previous iter fully consumed

#pragma unroll
        for (int p = 0; p < 4; p++) {
            const int d = p * 16 + lc0;
            float4 k4 = *(const float4*)(Kg + (size_t)(mbase + lr) * QKVD + d);
            float4 v4 = *(const float4*)(Vg + (size_t)(mbase + lr) * QKVD + d);
            KP[d + 0][lr] = k4.x; KP[d + 1][lr] = k4.y;
            KP[d + 2][lr] = k4.z; KP[d + 3][lr] = k4.w;
            *(float4*)&Vs[lr][d] = v4;
        }
        float4 bias[4];
#pragma unroll
        for (int i = 0; i < 4; i++)
            bias[i] = *(const float4*)(Bg + (size_t)(bm + r0 + i) * NN + mbase + tx * 4);
        __syncthreads();

        // S = 0.125 * Q K^T + bias
        float a[4][4] = {};
#pragma unroll
        for (int d = 0; d < 64; d++) {
            const float4 k = *(const float4*)&KP[d][tx * 4];
#pragma unroll
            for (int i = 0; i < 4; i++) {
                const float q = Qs[r0 + i][d];
                a[i][0] = fmaf(q, k.x, a[i][0]); a[i][1] = fmaf(q, k.y, a[i][1]);
                a[i][2] = fmaf(q, k.z, a[i][2]); a[i][3] = fmaf(q, k.w, a[i][3]);
            }
        }

        float p[4][4];
#pragma unroll
        for (int i = 0; i < 4; i++) {
            float s0 = fmaf(0.125f, a[i][0], bias[i].x);
            float s1 = fmaf(0.125f, a[i][1], bias[i].y);
            float s2 = fmaf(0.125f, a[i][2], bias[i].z);
            float s3 = fmaf(0.125f, a[i][3], bias[i].w);
            float mx = fmaxf(fmaxf(s0, s1), fmaxf(s2, s3));
#pragma unroll
            for (int o = 8; o; o >>= 1) mx = fmaxf(mx, __shfl_xor_sync(0xffffffffu, mx, o));
            const float nm = fmaxf(rmax[i], mx);
            const float al = __expf(rmax[i] - nm);
            rmax[i] = nm;
            p[i][0] = __expf(s0 - nm); p[i][1] = __expf(s1 - nm);
            p[i][2] = __expf(s2 - nm); p[i][3] = __expf(s3 - nm);
            float ls = p[i][0] + p[i][1] + p[i][2] + p[i][3];
#pragma unroll
            for (int o = 8; o; o >>= 1) ls += __shfl_xor_sync(0xffffffffu, ls, o);
            rsum[i] = rsum[i] * al + ls;
            O[i][0] *= al; O[i][1] *= al; O[i][2] *= al; O[i][3] *= al;
        }

        __syncthreads();  // done reading KP as K^T
#pragma unroll
        for (int i = 0; i < 4; i++)
            *(float4*)&KP[r0 + i][tx * 4] = make_float4(p[i][0], p[i][1], p[i][2], p[i][3]);
        __syncthreads();  // P visible

        // O += P V
#pragma unroll
        for (int m = 0; m < 64; m++) {
            const float4 v = *(const float4*)&Vs[m][tx * 4];
#pragma unroll
            for (int i = 0; i < 4; i++) {
                const float pa = KP[r0 + i][m];
                O[i][0] = fmaf(pa, v.x, O[i][0]); O[i][1] = fmaf(pa, v.y, O[i][1]);
                O[i][2] = fmaf(pa, v.z, O[i][2]); O[i][3] = fmaf(pa, v.w, O[i][3]);
            }
        }
    }

#pragma unroll
    for (int i = 0; i < 4; i++) {
        const float inv = 1.0f / rsum[i];
        *(float4*)(out + (size_t)(bm + r0 + i) * DIM + h * HD + tx * 4) =
            make_float4(O[i][0] * inv, O[i][1] * inv, O[i][2] * inv, O[i][3] * inv);
    }
}

// ---------------------------------------------------------------------------
extern "C" void kernel_launch(void* const* d_in, const int* in_sizes, int n_in,
                              void* d_out, int out_size) {
    const float* x    = (const float*)d_in[0];
    // d_in[1] = x_reg : unused by the reference
    const float* locs = (const float*)d_in[2];
    const float* Wqkv = (const float*)d_in[3];
    const float* Wloc = (const float*)d_in[4];
    const float* bloc = (const float*)d_in[5];
    float* out = (float*)d_out;

    fused_pre<<<QKV_BLOCKS + LOC_BLOCKS, 256>>>(x, Wqkv, locs, Wloc, bloc);
    fused_attn<<<(NN / BM) * HEADS, 256>>>(out);
}

// round 4
// speedup vs baseline: 1.4998x; 1.0246x over previous
#include <cuda_runtime.h>
#include <math.h>

#define NN 1024
#define DIM 512
#define QKVD 1536
#define HEADS 8
#define HD 64
#define BM 64
#define NSPLIT 2
#define MPART (NN / NSPLIT)   // 512 keys per split

#define QKV_MT 128
#define QKV_NT 64
#define QKV_BLOCKS ((NN / QKV_MT) * (QKVD / QKV_NT))   // 192
#define LOC_BLOCKS (NN * NN / 256)                      // 4096

// Scratch (static device allocation only).
__device__ float g_qkv[NN * QKVD];               // [n, 3*512]
__device__ float g_S[(size_t)HEADS * NN * NN];   // [h, n, m] location bias (log)
__device__ float g_Op[NSPLIT][HEADS][NN][HD];    // partial O (unnormalized)
__device__ float g_mx[NSPLIT][HEADS][NN];        // partial rowmax
__device__ float g_ls[NSPLIT][HEADS][NN];        // partial rowsum

// ---------------------------------------------------------------------------
// K1 (combined): QKV GEMM blocks + location-bias blocks in one launch.
// ---------------------------------------------------------------------------
struct SmemQkv {
    float As[8][132];
    float Bs[8][68];
};
struct SmemLoc {
    float sW[8][64];
    float sb[8];
};

__global__ void __launch_bounds__(256) fused_pre(const float* __restrict__ x,
                                                 const float* __restrict__ W,
                                                 const float* __restrict__ locs,
                                                 const float* __restrict__ Wl,
                                                 const float* __restrict__ bl) {
    __shared__ char smem_raw[sizeof(SmemQkv)];
    const int t = threadIdx.x;

    if (blockIdx.x < QKV_BLOCKS) {
        SmemQkv* s = (SmemQkv*)smem_raw;
        const int qb = blockIdx.x;
        const int bm = (qb % (NN / QKV_MT)) * QKV_MT;
        const int bn = (qb / (NN / QKV_MT)) * QKV_NT;
        const int tx = t & 15, ty = t >> 4;

        const int ar = t >> 1;
        const int akc = (t & 1) * 4;
        const int br = t >> 1;
        const int bkc = (t & 1) * 4;

        const float* Ap = x + (size_t)(bm + ar) * DIM + akc;
        const float* Bp = W + (size_t)(bn + (br & 63)) * DIM + bkc;

        float4 ra = *(const float4*)Ap;
        float4 rb = (t < 128) ? *(const float4*)Bp : make_float4(0, 0, 0, 0);

        float acc[8][4] = {};
        for (int k0 = 0; k0 < DIM; k0 += 8) {
            __syncthreads();
            s->As[akc + 0][ar] = ra.x; s->As[akc + 1][ar] = ra.y;
            s->As[akc + 2][ar] = ra.z; s->As[akc + 3][ar] = ra.w;
            if (t < 128) {
                s->Bs[bkc + 0][br] = rb.x; s->Bs[bkc + 1][br] = rb.y;
                s->Bs[bkc + 2][br] = rb.z; s->Bs[bkc + 3][br] = rb.w;
            }
            __syncthreads();
            if (k0 + 8 < DIM) {
                ra = *(const float4*)(Ap + k0 + 8);
                if (t < 128) rb = *(const float4*)(Bp + k0 + 8);
            }
#pragma unroll
            for (int k = 0; k < 8; k++) {
                float4 a0 = *(const float4*)&s->As[k][ty * 8];
                float4 a1 = *(const float4*)&s->As[k][ty * 8 + 4];
                float4 b  = *(const float4*)&s->Bs[k][tx * 4];
                const float av[8] = {a0.x, a0.y, a0.z, a0.w, a1.x, a1.y, a1.z, a1.w};
#pragma unroll
                for (int i = 0; i < 8; i++) {
                    acc[i][0] = fmaf(av[i], b.x, acc[i][0]);
                    acc[i][1] = fmaf(av[i], b.y, acc[i][1]);
                    acc[i][2] = fmaf(av[i], b.z, acc[i][2]);
                    acc[i][3] = fmaf(av[i], b.w, acc[i][3]);
                }
            }
        }
#pragma unroll
        for (int i = 0; i < 8; i++)
            *(float4*)&g_qkv[(size_t)(bm + ty * 8 + i) * QKVD + bn + tx * 4] =
                make_float4(acc[i][0], acc[i][1], acc[i][2], acc[i][3]);
    } else {
        SmemLoc* s = (SmemLoc*)smem_raw;
        for (int i = t; i < 512; i += 256) s->sW[i >> 6][i & 63] = Wl[i];
        if (t < 8) s->sb[t] = bl[t];
        __syncthreads();

        const int lid = blockIdx.x - QKV_BLOCKS;
        const int n = lid >> 2;
        const int m = (lid & 3) * 256 + t;

        const float4 bn = ((const float4*)locs)[n];
        const float4 bm = ((const float4*)locs)[m];
        const float wn = bn.z - bn.x + 1.0f, hn = bn.w - bn.y + 1.0f;
        const float wm = bm.z - bm.x + 1.0f, hm = bm.w - bm.y + 1.0f;
        const float cxn = 0.5f * (bn.x + bn.z), cyn = 0.5f * (bn.y + bn.w);
        const float cxm = 0.5f * (bm.x + bm.z), cym = 0.5f * (bm.y + bm.w);

        float pos[4];
        pos[0] = __logf(fmaxf(fabsf((cxn - cxm) / wn), 1e-3f));
        pos[1] = __logf(fmaxf(fabsf((cyn - cym) / hn), 1e-3f));
        pos[2] = __logf(wm / wn);
        pos[3] = __logf(hm / hn);

        const float invd[8] = {100.0f, 42.1696503f, 17.7827941f, 7.49894209f,
                               3.16227766f, 1.33352143f, 0.562341325f, 0.237137371f};

        float acc[8];
#pragma unroll
        for (int h = 0; h < 8; h++) acc[h] = s->sb[h];

#pragma unroll
        for (int g = 0; g < 4; g++) {
#pragma unroll
            for (int j = 0; j < 8; j++) {
                float sn, cs;
                __sincosf(pos[g] * invd[j], &sn, &cs);
#pragma unroll
                for (int h = 0; h < 8; h++)
                    acc[h] = fmaf(sn, s->sW[h][g * 16 + j],
                                  fmaf(cs, s->sW[h][g * 16 + 8 + j], acc[h]));
            }
        }
        const size_t base = (size_t)n * NN + m;
#pragma unroll
        for (int h = 0; h < 8; h++)
            g_S[(size_t)h * NN * NN + base] = __logf(fmaxf(acc[h], 0.0f) + 1e-6f);
    }
}

// ---------------------------------------------------------------------------
// K2: split-KV flash attention. Block = (q-tile, head, split); 256 threads,
// 4x4 fragments over a 64x64 tile; each split covers 512 keys.
// ---------------------------------------------------------------------------
__global__ void __launch_bounds__(256) fused_attn() {
    __shared__ float Qs[64][64];
    __shared__ float KP[64][64];
    __shared__ float Vs[64][64];

    const int t  = threadIdx.x;
    const int tx = t & 15, ty = t >> 4;
    const int h   = blockIdx.x & 7;
    const int qt  = (blockIdx.x >> 3) & 15;
    const int sp  = blockIdx.x >> 7;
    const int bm  = qt * BM;
    const int r0  = ty * 4;
    const int m0g = sp * MPART;

    {
        const int qr = t >> 2;
        const int lc = (t & 3) * 4;
        const float* Q = g_qkv + (size_t)(bm + qr) * QKVD + h * HD;
#pragma unroll
        for (int p = 0; p < 4; p++)
            *(float4*)&Qs[qr][p * 16 + lc] = *(const float4*)(Q + p * 16 + lc);
    }

    float O[4][4] = {};
    float rmax[4] = {-INFINITY, -INFINITY, -INFINITY, -INFINITY};
    float rsum[4] = {};

    const float* Kg = g_qkv + DIM + h * HD;
    const float* Vg = g_qkv + 2 * DIM + h * HD;
    const float* Bg = g_S + (size_t)h * NN * NN;

    const int lr  = t >> 2;
    const int lc0 = (t & 3) * 4;

    for (int mt = 0; mt < MPART / 64; mt++) {
        const int mbase = m0g + mt * 64;
        __syncthreads();

#pragma unroll
        for (int p = 0; p < 4; p++) {
            const int d = p * 16 + lc0;
            float4 k4 = *(const float4*)(Kg + (size_t)(mbase + lr) * QKVD + d);
            float4 v4 = *(const float4*)(Vg + (size_t)(mbase + lr) * QKVD + d);
            KP[d + 0][lr] = k4.x; KP[d + 1][lr] = k4.y;
            KP[d + 2][lr] = k4.z; KP[d + 3][lr] = k4.w;
            *(float4*)&Vs[lr][d] = v4;
        }
        float4 bias[4];
#pragma unroll
        for (int i = 0; i < 4; i++)
            bias[i] = *(const float4*)(Bg + (size_t)(bm + r0 + i) * NN + mbase + tx * 4);
        __syncthreads();

        float a[4][4] = {};
#pragma unroll
        for (int d = 0; d < 64; d++) {
            const float4 k = *(const float4*)&KP[d][tx * 4];
#pragma unroll
            for (int i = 0; i < 4; i++) {
                const float q = Qs[r0 + i][d];
                a[i][0] = fmaf(q, k.x, a[i][0]); a[i][1] = fmaf(q, k.y, a[i][1]);
                a[i][2] = fmaf(q, k.z, a[i][2]); a[i][3] = fmaf(q, k.w, a[i][3]);
            }
        }

        float p[4][4];
#pragma unroll
        for (int i = 0; i < 4; i++) {
            float s0 = fmaf(0.125f, a[i][0], bias[i].x);
            float s1 = fmaf(0.125f, a[i][1], bias[i].y);
            float s2 = fmaf(0.125f, a[i][2], bias[i].z);
            float s3 = fmaf(0.125f, a[i][3], bias[i].w);
            float mx = fmaxf(fmaxf(s0, s1), fmaxf(s2, s3));
#pragma unroll
            for (int o = 8; o; o >>= 1) mx = fmaxf(mx, __shfl_xor_sync(0xffffffffu, mx, o));
            const float nm = fmaxf(rmax[i], mx);
            const float al = __expf(rmax[i] - nm);
            rmax[i] = nm;
            p[i][0] = __expf(s0 - nm); p[i][1] = __expf(s1 - nm);
            p[i][2] = __expf(s2 - nm); p[i][3] = __expf(s3 - nm);
            float ls = p[i][0] + p[i][1] + p[i][2] + p[i][3];
#pragma unroll
            for (int o = 8; o; o >>= 1) ls += __shfl_xor_sync(0xffffffffu, ls, o);
            rsum[i] = rsum[i] * al + ls;
            O[i][0] *= al; O[i][1] *= al; O[i][2] *= al; O[i][3] *= al;
        }

        __syncthreads();
#pragma unroll
        for (int i = 0; i < 4; i++)
            *(float4*)&KP[r0 + i][tx * 4] = make_float4(p[i][0], p[i][1], p[i][2], p[i][3]);
        __syncthreads();

#pragma unroll
        for (int m = 0; m < 64; m++) {
            const float4 v = *(const float4*)&Vs[m][tx * 4];
#pragma unroll
            for (int i = 0; i < 4; i++) {
                const float pa = KP[r0 + i][m];
                O[i][0] = fmaf(pa, v.x, O[i][0]); O[i][1] = fmaf(pa, v.y, O[i][1]);
                O[i][2] = fmaf(pa, v.z, O[i][2]); O[i][3] = fmaf(pa, v.w, O[i][3]);
            }
        }
    }

    // Write partial (unnormalized O, rowmax, rowsum)
#pragma unroll
    for (int i = 0; i < 4; i++) {
        const int n = bm + r0 + i;
        *(float4*)&g_Op[sp][h][n][tx * 4] = make_float4(O[i][0], O[i][1], O[i][2], O[i][3]);
        if (tx == 0) {
            g_mx[sp][h][n] = rmax[i];
            g_ls[sp][h][n] = rsum[i];
        }
    }
}

// ---------------------------------------------------------------------------
// K3: merge the NSPLIT partials. One warp per (h,n) row, 2 d-values per lane.
// ---------------------------------------------------------------------------
__global__ void __launch_bounds__(256) merge_k(float* __restrict__ out) {
    const int w = (blockIdx.x * 8) + (threadIdx.x >> 5);  // row id 0..8191
    const int lane = threadIdx.x & 31;
    const int h = w >> 10;
    const int n = w & 1023;

    const float m0 = g_mx[0][h][n], m1 = g_mx[1][h][n];
    const float mM = fmaxf(m0, m1);
    const float e0 = __expf(m0 - mM), e1 = __expf(m1 - mM);
    const float inv = 1.0f / (g_ls[0][h][n] * e0 + g_ls[1][h][n] * e1);

    const float2 o0 = *(const float2*)&g_Op[0][h][n][lane * 2];
    const float2 o1 = *(const float2*)&g_Op[1][h][n][lane * 2];
    float2 r;
    r.x = (o0.x * e0 + o1.x * e1) * inv;
    r.y = (o0.y * e0 + o1.y * e1) * inv;
    *(float2*)(out + (size_t)n * DIM + h * HD + lane * 2) = r;
}

// ---------------------------------------------------------------------------
extern "C" void kernel_launch(void* const* d_in, const int* in_sizes, int n_in,
                              void* d_out, int out_size) {
    const float* x    = (const float*)d_in[0];
    const float* locs = (const float*)d_in[2];
    const float* Wqkv = (const float*)d_in[3];
    const float* Wloc = (const float*)d_in[4];
    const float* bloc = (const float*)d_in[5];
    float* out = (float*)d_out;

    fused_pre<<<QKV_BLOCKS + LOC_BLOCKS, 256>>>(x, Wqkv, locs, Wloc, bloc);
    fused_attn<<<(NN / BM) * HEADS * NSPLIT, 256>>>();
    merge_k<<<HEADS * NN / 8, 256>>>(out);
}

// round 5
// speedup vs baseline: 1.5767x; 1.0513x over previous
#include <cuda_runtime.h>
#include <math.h>

#define NN 1024
#define DIM 512
#define QKVD 1536
#define HEADS 8
#define HD 64
#define BM 64
#define NSPLIT 2
#define MPART (NN / NSPLIT)

#define QKV_MT 128
#define QKV_NT 64
#define QKV_BLOCKS ((NN / QKV_MT) * (QKVD / QKV_NT))   // 8*24 = 192
#define LOC_BLOCKS (NN * NN / 256)                      // 4096

// Scratch (static device allocation only).
__device__ float g_qkv[NN * QKVD];               // [n, 3*512]
__device__ float g_S[(size_t)HEADS * NN * NN];   // [h, n, m] location bias (log)
__device__ float g_Op[NSPLIT][HEADS][NN][HD];
__device__ float g_mx[NSPLIT][HEADS][NN];
__device__ float g_ls[NSPLIT][HEADS][NN];

// ---------------------------------------------------------------------------
// tf32 helpers
// ---------------------------------------------------------------------------
__device__ __forceinline__ unsigned cvt_tf32(float f) {
    unsigned u;
    asm("cvt.rna.tf32.f32 %0, %1;" : "=r"(u) : "f"(f));
    return u;
}
__device__ __forceinline__ void split_tf32(float f, unsigned& hi, unsigned& lo) {
    hi = cvt_tf32(f);
    lo = cvt_tf32(f - __uint_as_float(hi));
}
__device__ __forceinline__ void mma_tf32(float* c, const unsigned* a, const unsigned* b) {
    asm volatile(
        "mma.sync.aligned.m16n8k8.row.col.f32.tf32.tf32.f32 "
        "{%0,%1,%2,%3}, {%4,%5,%6,%7}, {%8,%9}, {%0,%1,%2,%3};"
        : "+f"(c[0]), "+f"(c[1]), "+f"(c[2]), "+f"(c[3])
        : "r"(a[0]), "r"(a[1]), "r"(a[2]), "r"(a[3]), "r"(b[0]), "r"(b[1]));
}

// ---------------------------------------------------------------------------
// K1 (combined): tf32 QKV GEMM blocks + location-bias blocks, one launch.
// ---------------------------------------------------------------------------
struct SmemQkv {
    float As[QKV_MT][20];   // [m][k], BK=16, pad 20 (conflict-free frag reads)
    float Bs[QKV_NT][20];   // [n][k]
};
struct SmemLoc {
    float sW[8][64];
    float sb[8];
};

__global__ void __launch_bounds__(256) fused_pre(const float* __restrict__ x,
                                                 const float* __restrict__ W,
                                                 const float* __restrict__ locs,
                                                 const float* __restrict__ Wl,
                                                 const float* __restrict__ bl) {
    __shared__ char smem_raw[sizeof(SmemQkv)];
    const int t = threadIdx.x;

    if (blockIdx.x < QKV_BLOCKS) {
        // -------- tf32 GEMM: 128x64 tile, 8 warps (4m x 2n), warp 32x32 -----
        SmemQkv* s = (SmemQkv*)smem_raw;
        const int qb = blockIdx.x;
        const int bm = (qb % (NN / QKV_MT)) * QKV_MT;
        const int bn = (qb / (NN / QKV_MT)) * QKV_NT;
        const int w  = t >> 5, l = t & 31;
        const int wm = (w & 3) * 32;      // warp m offset
        const int wn = (w >> 2) * 32;     // warp n offset
        const int lq = l >> 2, lr = l & 3;

        const int arow = t >> 1;          // 0..127
        const int akc  = (t & 1) * 8;     // 0 | 8
        const float* Ap = x + (size_t)(bm + arow) * DIM + akc;
        const float* Bp = W + (size_t)(bn + (arow & 63)) * DIM + akc;

        float4 ra0 = *(const float4*)Ap;
        float4 ra1 = *(const float4*)(Ap + 4);
        float4 rb0 = make_float4(0, 0, 0, 0), rb1 = rb0;
        if (t < 128) { rb0 = *(const float4*)Bp; rb1 = *(const float4*)(Bp + 4); }

        float acc[2][4][4] = {};

        for (int kk = 0; kk < DIM; kk += 16) {
            __syncthreads();
            *(float4*)&s->As[arow][akc]     = ra0;
            *(float4*)&s->As[arow][akc + 4] = ra1;
            if (t < 128) {
                *(float4*)&s->Bs[arow & 63][akc]     = rb0;
                *(float4*)&s->Bs[arow & 63][akc + 4] = rb1;
            }
            __syncthreads();
            if (kk + 16 < DIM) {
                ra0 = *(const float4*)(Ap + kk + 16);
                ra1 = *(const float4*)(Ap + kk + 20);
                if (t < 128) {
                    rb0 = *(const float4*)(Bp + kk + 16);
                    rb1 = *(const float4*)(Bp + kk + 20);
                }
            }
#pragma unroll
            for (int ks = 0; ks < 16; ks += 8) {
                unsigned ahi[2][4], alo[2][4];
#pragma unroll
                for (int mi = 0; mi < 2; mi++) {
                    const int r = wm + mi * 16;
                    split_tf32(s->As[r + lq][ks + lr],          ahi[mi][0], alo[mi][0]);
                    split_tf32(s->As[r + lq + 8][ks + lr],      ahi[mi][1], alo[mi][1]);
                    split_tf32(s->As[r + lq][ks + lr + 4],      ahi[mi][2], alo[mi][2]);
                    split_tf32(s->As[r + lq + 8][ks + lr + 4],  ahi[mi][3], alo[mi][3]);
                }
#pragma unroll
                for (int ni = 0; ni < 4; ni++) {
                    unsigned bhi[2], blo[2];
                    const int c = wn + ni * 8 + lq;
                    split_tf32(s->Bs[c][ks + lr],     bhi[0], blo[0]);
                    split_tf32(s->Bs[c][ks + lr + 4], bhi[1], blo[1]);
#pragma unroll
                    for (int mi = 0; mi < 2; mi++) {
                        mma_tf32(acc[mi][ni], ahi[mi], bhi);
                        mma_tf32(acc[mi][ni], ahi[mi], blo);
                        mma_tf32(acc[mi][ni], alo[mi], bhi);
                    }
                }
            }
        }
        // Store: c0,c1 -> (row, col..col+1); c2,c3 -> (row+8, ...)
#pragma unroll
        for (int mi = 0; mi < 2; mi++)
#pragma unroll
            for (int ni = 0; ni < 4; ni++) {
                const int r = bm + wm + mi * 16 + lq;
                const int c = bn + wn + ni * 8 + lr * 2;
                *(float2*)&g_qkv[(size_t)r * QKVD + c] =
                    make_float2(acc[mi][ni][0], acc[mi][ni][1]);
                *(float2*)&g_qkv[(size_t)(r + 8) * QKVD + c] =
                    make_float2(acc[mi][ni][2], acc[mi][ni][3]);
            }
    } else {
        // ---------------- Location bias ------------------------------------
        SmemLoc* s = (SmemLoc*)smem_raw;
        for (int i = t; i < 512; i += 256) s->sW[i >> 6][i & 63] = Wl[i];
        if (t < 8) s->sb[t] = bl[t];
        __syncthreads();

        const int lid = blockIdx.x - QKV_BLOCKS;
        const int n = lid >> 2;
        const int m = (lid & 3) * 256 + t;

        const float4 bn = ((const float4*)locs)[n];
        const float4 bm = ((const float4*)locs)[m];
        const float wn = bn.z - bn.x + 1.0f, hn = bn.w - bn.y + 1.0f;
        const float wm = bm.z - bm.x + 1.0f, hm = bm.w - bm.y + 1.0f;
        const float cxn = 0.5f * (bn.x + bn.z), cyn = 0.5f * (bn.y + bn.w);
        const float cxm = 0.5f * (bm.x + bm.z), cym = 0.5f * (bm.y + bm.w);

        float pos[4];
        pos[0] = __logf(fmaxf(fabsf((cxn - cxm) / wn), 1e-3f));
        pos[1] = __logf(fmaxf(fabsf((cyn - cym) / hn), 1e-3f));
        pos[2] = __logf(wm / wn);
        pos[3] = __logf(hm / hn);

        const float invd[8] = {100.0f, 42.1696503f, 17.7827941f, 7.49894209f,
                               3.16227766f, 1.33352143f, 0.562341325f, 0.237137371f};

        float acc[8];
#pragma unroll
        for (int h = 0; h < 8; h++) acc[h] = s->sb[h];

#pragma unroll
        for (int g = 0; g < 4; g++) {
#pragma unroll
            for (int j = 0; j < 8; j++) {
                float sn, cs;
                __sincosf(pos[g] * invd[j], &sn, &cs);
#pragma unroll
                for (int h = 0; h < 8; h++)
                    acc[h] = fmaf(sn, s->sW[h][g * 16 + j],
                                  fmaf(cs, s->sW[h][g * 16 + 8 + j], acc[h]));
            }
        }
        const size_t base = (size_t)n * NN + m;
#pragma unroll
        for (int h = 0; h < 8; h++)
            g_S[(size_t)h * NN * NN + base] = __logf(fmaxf(acc[h], 0.0f) + 1e-6f);
    }
}

// ---------------------------------------------------------------------------
// K2: split-KV flash attention (scalar FFMA), unchanged from R4.
// ---------------------------------------------------------------------------
__global__ void __launch_bounds__(256) fused_attn() {
    __shared__ float Qs[64][64];
    __shared__ float KP[64][64];
    __shared__ float Vs[64][64];

    const int t  = threadIdx.x;
    const int tx = t & 15, ty = t >> 4;
    const int h   = blockIdx.x & 7;
    const int qt  = (blockIdx.x >> 3) & 15;
    const int sp  = blockIdx.x >> 7;
    const int bm  = qt * BM;
    const int r0  = ty * 4;
    const int m0g = sp * MPART;

    {
        const int qr = t >> 2;
        const int lc = (t & 3) * 4;
        const float* Q = g_qkv + (size_t)(bm + qr) * QKVD + h * HD;
#pragma unroll
        for (int p = 0; p < 4; p++)
            *(float4*)&Qs[qr][p * 16 + lc] = *(const float4*)(Q + p * 16 + lc);
    }

    float O[4][4] = {};
    float rmax[4] = {-INFINITY, -INFINITY, -INFINITY, -INFINITY};
    float rsum[4] = {};

    const float* Kg = g_qkv + DIM + h * HD;
    const float* Vg = g_qkv + 2 * DIM + h * HD;
    const float* Bg = g_S + (size_t)h * NN * NN;

    const int lr  = t >> 2;
    const int lc0 = (t & 3) * 4;

    for (int mt = 0; mt < MPART / 64; mt++) {
        const int mbase = m0g + mt * 64;
        __syncthreads();

#pragma unroll
        for (int p = 0; p < 4; p++) {
            const int d = p * 16 + lc0;
            float4 k4 = *(const float4*)(Kg + (size_t)(mbase + lr) * QKVD + d);
            float4 v4 = *(const float4*)(Vg + (size_t)(mbase + lr) * QKVD + d);
            KP[d + 0][lr] = k4.x; KP[d + 1][lr] = k4.y;
            KP[d + 2][lr] = k4.z; KP[d + 3][lr] = k4.w;
            *(float4*)&Vs[lr][d] = v4;
        }
        float4 bias[4];
#pragma unroll
        for (int i = 0; i < 4; i++)
            bias[i] = *(const float4*)(Bg + (size_t)(bm + r0 + i) * NN + mbase + tx * 4);
        __syncthreads();

        float a[4][4] = {};
#pragma unroll
        for (int d = 0; d < 64; d++) {
            const float4 k = *(const float4*)&KP[d][tx * 4];
#pragma unroll
            for (int i = 0; i < 4; i++) {
                const float q = Qs[r0 + i][d];
                a[i][0] = fmaf(q, k.x, a[i][0]); a[i][1] = fmaf(q, k.y, a[i][1]);
                a[i][2] = fmaf(q, k.z, a[i][2]); a[i][3] = fmaf(q, k.w, a[i][3]);
            }
        }

        float p[4][4];
#pragma unroll
        for (int i = 0; i < 4; i++) {
            float s0 = fmaf(0.125f, a[i][0], bias[i].x);
            float s1 = fmaf(0.125f, a[i][1], bias[i].y);
            float s2 = fmaf(0.125f, a[i][2], bias[i].z);
            float s3 = fmaf(0.125f, a[i][3], bias[i].w);
            float mx = fmaxf(fmaxf(s0, s1), fmaxf(s2, s3));
#pragma unroll
            for (int o = 8; o; o >>= 1) mx = fmaxf(mx, __shfl_xor_sync(0xffffffffu, mx, o));
            const float nm = fmaxf(rmax[i], mx);
            const float al = __expf(rmax[i] - nm);
            rmax[i] = nm;
            p[i][0] = __expf(s0 - nm); p[i][1] = __expf(s1 - nm);
            p[i][2] = __expf(s2 - nm); p[i][3] = __expf(s3 - nm);
            float ls = p[i][0] + p[i][1] + p[i][2] + p[i][3];
#pragma unroll
            for (int o = 8; o; o >>= 1) ls += __shfl_xor_sync(0xffffffffu, ls, o);
            rsum[i] = rsum[i] * al + ls;
            O[i][0] *= al; O[i][1] *= al; O[i][2] *= al; O[i][3] *= al;
        }

        __syncthreads();
#pragma unroll
        for (int i = 0; i < 4; i++)
            *(float4*)&KP[r0 + i][tx * 4] = make_float4(p[i][0], p[i][1], p[i][2], p[i][3]);
        __syncthreads();

#pragma unroll
        for (int m = 0; m < 64; m++) {
            const float4 v = *(const float4*)&Vs[m][tx * 4];
#pragma unroll
            for (int i = 0; i < 4; i++) {
                const float pa = KP[r0 + i][m];
                O[i][0] = fmaf(pa, v.x, O[i][0]); O[i][1] = fmaf(pa, v.y, O[i][1]);
                O[i][2] = fmaf(pa, v.z, O[i][2]); O[i][3] = fmaf(pa, v.w, O[i][3]);
            }
        }
    }

#pragma unroll
    for (int i = 0; i < 4; i++) {
        const int n = bm + r0 + i;
        *(float4*)&g_Op[sp][h][n][tx * 4] = make_float4(O[i][0], O[i][1], O[i][2], O[i][3]);
        if (tx == 0) {
            g_mx[sp][h][n] = rmax[i];
            g_ls[sp][h][n] = rsum[i];
        }
    }
}

// ---------------------------------------------------------------------------
// K3: merge split partials.
// ---------------------------------------------------------------------------
__global__ void __launch_bounds__(256) merge_k(float* __restrict__ out) {
    const int w = (blockIdx.x * 8) + (threadIdx.x >> 5);
    const int lane = threadIdx.x & 31;
    const int h = w >> 10;
    const int n = w & 1023;

    const float m0 = g_mx[0][h][n], m1 = g_mx[1][h][n];
    const float mM = fmaxf(m0, m1);
    const float e0 = __expf(m0 - mM), e1 = __expf(m1 - mM);
    const float inv = 1.0f / (g_ls[0][h][n] * e0 + g_ls[1][h][n] * e1);

    const float2 o0 = *(const float2*)&g_Op[0][h][n][lane * 2];
    const float2 o1 = *(const float2*)&g_Op[1][h][n][lane * 2];
    float2 r;
    r.x = (o0.x * e0 + o1.x * e1) * inv;
    r.y = (o0.y * e0 + o1.y * e1) * inv;
    *(float2*)(out + (size_t)n * DIM + h * HD + lane * 2) = r;
}

// ---------------------------------------------------------------------------
extern "C" void kernel_launch(void* const* d_in, const int* in_sizes, int n_in,
                              void* d_out, int out_size) {
    const float* x    = (const float*)d_in[0];
    const float* locs = (const float*)d_in[2];
    const float* Wqkv = (const float*)d_in[3];
    const float* Wloc = (const float*)d_in[4];
    const float* bloc = (const float*)d_in[5];
    float* out = (float*)d_out;

    fused_pre<<<QKV_BLOCKS + LOC_BLOCKS, 256>>>(x, Wqkv, locs, Wloc, bloc);
    fused_attn<<<(NN / BM) * HEADS * NSPLIT, 256>>>();
    merge_k<<<HEADS * NN / 8, 256>>>(out);
}